// round 2
// baseline (speedup 1.0000x reference)
#include <cuda_runtime.h>

// DNAShapeNet fused kernel, R2: packed f32x2 (FFMA2) convolutions.
// 4x (Conv1d + ReLU + BN) + per-position MLP, fully fused in smem.
// B=128, S=8192, channels 4->32->32->32->32, kernels {3,3,5,7}, MLP 32->16->1.

#define BATCH    128
#define SEQ      8192
#define TSIZE    512
#define NTHREADS 512
#define WPAD     544
#define HALO     7

typedef unsigned long long ull;

// ---- smem layout (float offsets) ----
#define OFF_BUFA 0
#define OFF_BUFB (OFF_BUFA + 32*WPAD)
#define OFF_W0   (OFF_BUFB + 32*WPAD)
#define OFF_W1   (OFF_W0 + 384)
#define OFF_W2   (OFF_W1 + 3072)
#define OFF_W3   (OFF_W2 + 5120)
#define OFF_SC   (OFF_W3 + 7168)
#define OFF_SH   (OFF_SC + 128)
#define OFF_BI   (OFF_SH + 128)
#define OFF_FW1  (OFF_BI + 128)
#define OFF_FB1  (OFF_FW1 + 512)
#define OFF_FW2  (OFF_FB1 + 16)
#define OFF_FB2  (OFF_FW2 + 16)
#define SMEM_FLOATS (OFF_FB2 + 1)
#define SMEM_BYTES  (SMEM_FLOATS * 4)

struct Ptrs {
    const float* x;
    const float* w[4];
    const float* b[4];
    const float* g[4];
    const float* bb[4];
    const float* rm[4];
    const float* rv[4];
    const float* fw1;
    const float* fb1;
    const float* fw2;
    const float* fb2;
};

__device__ __forceinline__ ull pack2(float lo, float hi) {
    ull r;
    asm("mov.b64 %0, {%1, %2};" : "=l"(r) : "f"(lo), "f"(hi));
    return r;
}
__device__ __forceinline__ void unpack2(ull v, float& lo, float& hi) {
    asm("mov.b64 {%0, %1}, %2;" : "=f"(lo), "=f"(hi) : "l"(v));
}
__device__ __forceinline__ ull fma2(ull a, ull b, ull c) {
    ull d;
    asm("fma.rn.f32x2 %0, %1, %2, %3;" : "=l"(d) : "l"(a), "l"(b), "l"(c));
    return d;
}

// Process CHP output pairs for one input channel.
// vin: aligned pair pointer; wp: K broadcast weight pairs; acc: CHP pair accs.
// Tap t uses shift s = t + DELTA relative to the aligned base:
//   even s=2m -> v[p+m] ; odd s=2m+1 -> w[p+m] = {v[p+m].hi, v[p+m+1].lo}
template<int K, int DELTA, int CHP, int E>
__device__ __forceinline__ void conv_chunk(const ull* __restrict__ vin,
                                           const ull* __restrict__ wp,
                                           ull* __restrict__ acc)
{
    ull v[CHP + E];
#pragma unroll
    for (int i = 0; i < CHP + E; ++i) v[i] = vin[i];

    ull w[CHP + E - 1];
#pragma unroll
    for (int q = 0; q < CHP + E - 1; ++q) {
        float lo0, hi0, lo1, hi1;
        unpack2(v[q], lo0, hi0);
        unpack2(v[q + 1], lo1, hi1);
        w[q] = pack2(hi0, lo1);
    }

#pragma unroll
    for (int t = 0; t < K; ++t) {
        constexpr int D = DELTA;
        const int s = t + D;
#pragma unroll
        for (int p = 0; p < CHP; ++p) {
            ull op = (s & 1) ? w[p + (s >> 1)] : v[p + (s >> 1)];
            acc[p] = fma2(op, wp[t], acc[p]);
        }
    }
}

// One conv+ReLU+BN layer, smem -> smem, packed-pair math.
// Thread (co, j) computes channel co at 34 positions starting at LOFF + j*34.
template <int CIN, int K, int WOUT, int LOFF, int DELTA>
__device__ __forceinline__ void conv_layer(
    const float* __restrict__ sin, float* __restrict__ sout,
    const float* __restrict__ wgt,
    const float* __restrict__ sc, const float* __restrict__ sh,
    const float* __restrict__ bi,
    int co, int j, int seq_base)
{
    constexpr int H = K / 2;
    constexpr int E = (DELTA + K) / 2;     // extra pairs needed beyond CHP
    constexpr int PAIRS = 17;              // 34 positions per thread

    ull acc[PAIRS];
    const ull z = pack2(0.f, 0.f);
#pragma unroll
    for (int p = 0; p < PAIRS; ++p) acc[p] = z;

    const int abase = (LOFF - H - DELTA) + j * 34;   // even by construction
    const float* wrow = wgt + co * (CIN * K);

#pragma unroll 1
    for (int cin = 0; cin < CIN; ++cin) {
        ull wp[K];
#pragma unroll
        for (int t = 0; t < K; ++t) {
            float wv = wrow[cin * K + t];
            wp[t] = pack2(wv, wv);
        }
        const ull* vin = (const ull*)(sin + cin * WPAD + abase);
        conv_chunk<K, DELTA, 9, E>(vin,     wp, acc);
        conv_chunk<K, DELTA, 8, E>(vin + 9, wp, acc + 9);
    }

    const float scale = sc[co];
    const float shift = sh[co];
    const float bias  = bi[co];
    float* orow = sout + co * WPAD;

#pragma unroll
    for (int p = 0; p < PAIRS; ++p) {
        float lo, hi;
        unpack2(acc[p], lo, hi);
#pragma unroll
        for (int e = 0; e < 2; ++e) {
            float a = e ? hi : lo;
            int pl = j * 34 + 2 * p + e;
            if (pl < WOUT) {
                int u = LOFF + pl;
                int seq = seq_base + u;
                float y = fmaxf(a + bias, 0.f);
                orow[u] = (seq >= 0 && seq < SEQ) ? fmaf(y, scale, shift) : 0.f;
            }
        }
    }
}

__global__ void __launch_bounds__(NTHREADS, 1)
dna_fused_kernel(Ptrs P, float* __restrict__ out)
{
    extern __shared__ float sm[];
    const int tid = threadIdx.x;
    const int ts  = blockIdx.x * TSIZE;
    const int b   = blockIdx.y;
    const int seq_base = ts - HALO;

    float* bufA = sm + OFF_BUFA;
    float* bufB = sm + OFF_BUFB;
    float* sW[4] = { sm + OFF_W0, sm + OFF_W1, sm + OFF_W2, sm + OFF_W3 };
    float* sSC = sm + OFF_SC;
    float* sSH = sm + OFF_SH;
    float* sBI = sm + OFF_BI;
    float* sFW1 = sm + OFF_FW1;
    float* sFB1 = sm + OFF_FB1;
    float* sFW2 = sm + OFF_FW2;
    float* sFB2 = sm + OFF_FB2;

    const int wn[4] = { 32 * 4 * 3, 32 * 32 * 3, 32 * 32 * 5, 32 * 32 * 7 };
#pragma unroll
    for (int l = 0; l < 4; ++l)
        for (int i = tid; i < wn[l]; i += NTHREADS) sW[l][i] = P.w[l][i];

    for (int i = tid; i < 16 * 32; i += NTHREADS) sFW1[i] = P.fw1[i];
    if (tid < 16) { sFB1[tid] = P.fb1[tid]; sFW2[tid] = P.fw2[tid]; }
    if (tid == 0) sFB2[0] = P.fb2[0];

    if (tid < 128) {
        int l = tid >> 5, c = tid & 31;
        float inv = P.g[l][c] * rsqrtf(P.rv[l][c] + 1e-5f);
        sSC[tid] = inv;
        sSH[tid] = P.bb[l][c] - P.rm[l][c] * inv;
        sBI[tid] = P.b[l][c];
    }

    constexpr int WIN = TSIZE + 2 * HALO;   // 526
    for (int idx = tid; idx < 4 * WIN; idx += NTHREADS) {
        int cin = idx / WIN;
        int u = idx - cin * WIN;
        int seq = seq_base + u;
        bufA[cin * WPAD + u] =
            (seq >= 0 && seq < SEQ) ? P.x[(b * 4 + cin) * SEQ + seq] : 0.f;
    }
    __syncthreads();

    const int co = tid >> 4;
    const int j  = tid & 15;

    // aligned bases (LOFF-H-DELTA): L0:0  L1:0(delta=1)  L2:2  L3:4  — all even
    conv_layer<4, 3, 524, 1, 0>(bufA, bufB, sW[0], sSC +  0, sSH +  0, sBI +  0, co, j, seq_base);
    __syncthreads();
    conv_layer<32, 3, 522, 2, 1>(bufB, bufA, sW[1], sSC + 32, sSH + 32, sBI + 32, co, j, seq_base);
    __syncthreads();
    conv_layer<32, 5, 518, 4, 0>(bufA, bufB, sW[2], sSC + 64, sSH + 64, sBI + 64, co, j, seq_base);
    __syncthreads();
    conv_layer<32, 7, 512, 7, 0>(bufB, bufA, sW[3], sSC + 96, sSH + 96, sBI + 96, co, j, seq_base);
    __syncthreads();

    // ---- per-position MLP: 32 -> 16 (ReLU) -> 1, packed pairs ----
    float yc[32];
#pragma unroll
    for (int c = 0; c < 32; ++c) yc[c] = bufA[c * WPAD + HALO + tid];

    ull yp[16];
#pragma unroll
    for (int i = 0; i < 16; ++i) yp[i] = pack2(yc[2 * i], yc[2 * i + 1]);

    float o = sFB2[0];
#pragma unroll
    for (int i = 0; i < 16; ++i) {
        ull hp = pack2(sFB1[i], 0.f);
        const ull* fwp = (const ull*)(sFW1 + i * 32);
#pragma unroll
        for (int c = 0; c < 16; ++c) hp = fma2(fwp[c], yp[c], hp);
        float hlo, hhi;
        unpack2(hp, hlo, hhi);
        float h = hlo + hhi;
        o = fmaf(fmaxf(h, 0.f), sFW2[i], o);
    }
    out[b * SEQ + ts + tid] = o;
}

extern "C" void kernel_launch(void* const* d_in, const int* in_sizes, int n_in,
                              void* d_out, int out_size)
{
    Ptrs P;
    P.x = (const float*)d_in[0];
    for (int l = 0; l < 4; ++l) {
        P.w[l]  = (const float*)d_in[1 + 6 * l];
        P.b[l]  = (const float*)d_in[2 + 6 * l];
        P.g[l]  = (const float*)d_in[3 + 6 * l];
        P.bb[l] = (const float*)d_in[4 + 6 * l];
        P.rm[l] = (const float*)d_in[5 + 6 * l];
        P.rv[l] = (const float*)d_in[6 + 6 * l];
    }
    P.fw1 = (const float*)d_in[25];
    P.fb1 = (const float*)d_in[26];
    P.fw2 = (const float*)d_in[27];
    P.fb2 = (const float*)d_in[28];

    cudaFuncSetAttribute(dna_fused_kernel,
                         cudaFuncAttributeMaxDynamicSharedMemorySize, SMEM_BYTES);

    dim3 grid(SEQ / TSIZE, BATCH);
    dna_fused_kernel<<<grid, NTHREADS, SMEM_BYTES>>>(P, (float*)d_out);
}